// round 3
// baseline (speedup 1.0000x reference)
#include <cuda_runtime.h>

#define FULLMASK 0xffffffffu

namespace {
constexpr int H = 32;
constexpr int T = 512;
constexpr int D = 6;
constexpr int B = 4096;
constexpr int NB = 4;                 // batch samples per warp
constexpr int NJOBS = B / NB;         // 1024 warp-jobs
constexpr int WARPS = 7;
constexpr int TPB = WARPS * 32;       // 224 threads
constexpr int GRID = 148;             // one block per SM
}

// Preprocessed weights (permuted: row r = 4*j + gate, transposed to [k][128])
__device__ __align__(16) float g_W0Tx[D * 128];
__device__ __align__(16) float g_W0Th[H * 128];
__device__ __align__(16) float g_W1T[2 * H * 128];
__device__ __align__(16) float g_B0[128];
__device__ __align__(16) float g_B1[128];

__global__ void prep_kernel(const float* __restrict__ Wih0, const float* __restrict__ Whh0,
                            const float* __restrict__ bih0, const float* __restrict__ bhh0,
                            const float* __restrict__ Wih1, const float* __restrict__ Whh1,
                            const float* __restrict__ bih1, const float* __restrict__ bhh1) {
    int r = threadIdx.x;          // 0..127, new row index r = 4*j + g
    if (r >= 128) return;
    int j = r >> 2;
    int g = r & 3;
    int orig = g * H + j;         // original gate-major row
    g_B0[r] = bih0[orig] + bhh0[orig];
    g_B1[r] = bih1[orig] + bhh1[orig];
#pragma unroll
    for (int k = 0; k < D; k++) g_W0Tx[k * 128 + r] = Wih0[orig * D + k];
#pragma unroll
    for (int k = 0; k < H; k++) g_W0Th[k * 128 + r] = Whh0[orig * H + k];
#pragma unroll
    for (int k = 0; k < H; k++) g_W1T[k * 128 + r] = Wih1[orig * H + k];
#pragma unroll
    for (int k = 0; k < H; k++) g_W1T[(H + k) * 128 + r] = Whh1[orig * H + k];
}

// ---- packed f32x2 helpers (Blackwell FFMA2 path) ----
__device__ __forceinline__ unsigned long long dup2(float v) {
    unsigned long long r;
    asm("mov.b64 %0, {%1, %1};" : "=l"(r) : "f"(v));
    return r;
}
__device__ __forceinline__ unsigned long long pack2(float lo, float hi) {
    unsigned long long r;
    asm("mov.b64 %0, {%1, %2};" : "=l"(r) : "f"(lo), "f"(hi));
    return r;
}
__device__ __forceinline__ void unpack2(unsigned long long v, float& lo, float& hi) {
    asm("mov.b64 {%0, %1}, %2;" : "=f"(lo), "=f"(hi) : "l"(v));
}
__device__ __forceinline__ void fma2(unsigned long long& acc, unsigned long long a,
                                     unsigned long long b) {
    asm("fma.rn.f32x2 %0, %1, %2, %0;" : "+l"(acc) : "l"(a), "l"(b));
}

__device__ __forceinline__ float fast_sigmoid(float x) {
    float e;
    asm("ex2.approx.ftz.f32 %0, %1;" : "=f"(e) : "f"(-1.4426950408889634f * x));
    float r;
    asm("rcp.approx.ftz.f32 %0, %1;" : "=f"(r) : "f"(1.0f + e));
    return r;
}

__device__ __forceinline__ float fast_tanh(float x) {
    // tanh(x) = 2*sigmoid(2x) - 1
    return fmaf(2.0f, fast_sigmoid(2.0f * x), -1.0f);
}

__global__ void __launch_bounds__(TPB, 1)
lstm_kernel(const float* __restrict__ x,
            const float* __restrict__ gamma,
            const float* __restrict__ beta,
            float* __restrict__ out) {
    // Exactly 48KB static shared: recurrent weights only.
    __shared__ __align__(16) float sW0Th[H * 128];       // 16 KB
    __shared__ __align__(16) float sW1T[2 * H * 128];    // 32 KB

    for (int i = threadIdx.x; i < H * 128; i += TPB) sW0Th[i] = g_W0Th[i];
    for (int i = threadIdx.x; i < 2 * H * 128; i += TPB) sW1T[i] = g_W1T[i];
    __syncthreads();

    const int w = threadIdx.x >> 5;
    const int lane = threadIdx.x & 31;
    const int job = w * GRID + (int)blockIdx.x;   // near-perfect balance across 148 SMs
    if (job >= NJOBS) return;
    const int sBase = job * NB;

    // Per-lane constants in registers: gate pairs (i,f) and (g,o) as packed f32x2
    const ulonglong2 bias0 = *reinterpret_cast<const ulonglong2*>(&g_B0[4 * lane]);
    const ulonglong2 bias1 = *reinterpret_cast<const ulonglong2*>(&g_B1[4 * lane]);
    ulonglong2 wx[D];
#pragma unroll
    for (int k = 0; k < D; k++)
        wx[k] = *reinterpret_cast<const ulonglong2*>(&g_W0Tx[k * 128 + 4 * lane]);

    // x streaming: lanes 0..23 each carry one (sample, dim) element per step
    const float* xbase = x + (size_t)sBase * T * D;
    const int xs = lane / 6;
    const int xd = lane - xs * 6;
    const bool xact = lane < 24;
    float xnext = xact ? xbase[(size_t)xs * (T * D) + xd] : 0.0f;

    float h0[NB], c0[NB], h1[NB], c1[NB];
#pragma unroll
    for (int s = 0; s < NB; s++) { h0[s] = 0.f; c0[s] = 0.f; h1[s] = 0.f; c1[s] = 0.f; }

    for (int t = 0; t < T; t++) {
        const float xcur = xnext;
        const int tn = (t + 1 < T) ? (t + 1) : t;
        xnext = xact ? xbase[(size_t)xs * (T * D) + (size_t)tn * D + xd] : 0.0f;

        // ---------------- layer 0 ----------------
        unsigned long long aif[NB], ago[NB];
#pragma unroll
        for (int s = 0; s < NB; s++) { aif[s] = bias0.x; ago[s] = bias0.y; }

#pragma unroll
        for (int k = 0; k < D; k++) {
            const ulonglong2 wv = wx[k];
#pragma unroll
            for (int s = 0; s < NB; s++) {
                const unsigned long long v2 =
                    dup2(__shfl_sync(FULLMASK, xcur, s * 6 + k));
                fma2(aif[s], v2, wv.x);
                fma2(ago[s], v2, wv.y);
            }
        }
#pragma unroll 8
        for (int k = 0; k < H; k++) {
            const ulonglong2 wv =
                *reinterpret_cast<const ulonglong2*>(&sW0Th[k * 128 + 4 * lane]);
#pragma unroll
            for (int s = 0; s < NB; s++) {
                const unsigned long long v2 = dup2(__shfl_sync(FULLMASK, h0[s], k));
                fma2(aif[s], v2, wv.x);
                fma2(ago[s], v2, wv.y);
            }
        }
#pragma unroll
        for (int s = 0; s < NB; s++) {
            float ai, af, ag, ao;
            unpack2(aif[s], ai, af);
            unpack2(ago[s], ag, ao);
            const float ig = fast_sigmoid(ai);
            const float fg = fast_sigmoid(af);
            const float gg = fast_tanh(ag);
            const float og = fast_sigmoid(ao);
            const float c = fmaf(fg, c0[s], ig * gg);
            c0[s] = c;
            h0[s] = og * fast_tanh(c);
        }

        // ---------------- layer 1 ----------------
#pragma unroll
        for (int s = 0; s < NB; s++) { aif[s] = bias1.x; ago[s] = bias1.y; }

#pragma unroll 8
        for (int k = 0; k < H; k++) {
            const ulonglong2 wv =
                *reinterpret_cast<const ulonglong2*>(&sW1T[k * 128 + 4 * lane]);
#pragma unroll
            for (int s = 0; s < NB; s++) {
                const unsigned long long v2 = dup2(__shfl_sync(FULLMASK, h0[s], k));
                fma2(aif[s], v2, wv.x);
                fma2(ago[s], v2, wv.y);
            }
        }
#pragma unroll 8
        for (int k = 0; k < H; k++) {
            const ulonglong2 wv =
                *reinterpret_cast<const ulonglong2*>(&sW1T[(H + k) * 128 + 4 * lane]);
#pragma unroll
            for (int s = 0; s < NB; s++) {
                const unsigned long long v2 = dup2(__shfl_sync(FULLMASK, h1[s], k));
                fma2(aif[s], v2, wv.x);
                fma2(ago[s], v2, wv.y);
            }
        }
#pragma unroll
        for (int s = 0; s < NB; s++) {
            float ai, af, ag, ao;
            unpack2(aif[s], ai, af);
            unpack2(ago[s], ag, ao);
            const float ig = fast_sigmoid(ai);
            const float fg = fast_sigmoid(af);
            const float gg = fast_tanh(ag);
            const float og = fast_sigmoid(ao);
            const float c = fmaf(fg, c1[s], ig * gg);
            c1[s] = c;
            h1[s] = og * fast_tanh(c);
        }
    }

    // ---------------- LayerNorm over H=32 (one warp = one row) ----------------
    const float gam = gamma[lane];
    const float bet = beta[lane];
#pragma unroll
    for (int s = 0; s < NB; s++) {
        const float v = h1[s];
        float sum = v;
#pragma unroll
        for (int off = 16; off > 0; off >>= 1) sum += __shfl_xor_sync(FULLMASK, sum, off);
        const float mu = sum * (1.0f / 32.0f);
        const float dd = v - mu;
        float sq = dd * dd;
#pragma unroll
        for (int off = 16; off > 0; off >>= 1) sq += __shfl_xor_sync(FULLMASK, sq, off);
        const float var = sq * (1.0f / 32.0f);
        out[(size_t)(sBase + s) * H + lane] = fmaf(dd * rsqrtf(var + 1e-5f), gam, bet);
    }
}

extern "C" void kernel_launch(void* const* d_in, const int* in_sizes, int n_in,
                              void* d_out, int out_size) {
    const float* x     = (const float*)d_in[0];
    const float* Wih0  = (const float*)d_in[1];
    const float* Whh0  = (const float*)d_in[2];
    const float* bih0  = (const float*)d_in[3];
    const float* bhh0  = (const float*)d_in[4];
    const float* Wih1  = (const float*)d_in[5];
    const float* Whh1  = (const float*)d_in[6];
    const float* bih1  = (const float*)d_in[7];
    const float* bhh1  = (const float*)d_in[8];
    const float* gam   = (const float*)d_in[9];
    const float* bet   = (const float*)d_in[10];
    float* out = (float*)d_out;

    prep_kernel<<<1, 128>>>(Wih0, Whh0, bih0, bhh0, Wih1, Whh1, bih1, bhh1);
    lstm_kernel<<<GRID, TPB>>>(x, gam, bet, out);
}